// round 11
// baseline (speedup 1.0000x reference)
#include <cuda_runtime.h>

// ---------------- problem dims ----------------
constexpr int B_   = 8;
constexpr int IMG_ = 224;
constexpr int G_   = 14;
constexpr int N_   = 196;   // G*G patches
constexpr int PD_  = 256;   // 16*16 patch dim
constexpr int D_   = 128;
constexpr int DFF_ = 256;
constexpr int C_   = 1000;
constexpr int M_   = B_ * N_;   // 1568 token rows

constexpr float NEGBIG = -1e30f;

// ---------------- scratch ----------------
__device__ float g_h[M_ * D_];
__device__ float g_qkv[3 * M_ * D_];
__device__ float g_S[B_ * N_ * N_];
__device__ float g_m[M_];
__device__ float g_pool[B_ * D_];

// epilogue modes
enum {
    EPI_STORE = 0,       // plain store
    EPI_POS_M = 1,       // v = acc + pos[(r%196)*ldo+cc]; also write rowmax -> mout
    EPI_SUBROW = 2,      // v = acc - aux[r]
    EPI_SUBROW_TAU = 3,  // v = max(acc - aux[r], tau[0])
    EPI_RESID_M = 4      // v = max(O_old, acc - rowmax(acc)); write rowmax(v) -> mout
};

// =====================================================================
// Template A (R7-exact): BK=16, column-major As — best for embed/qkv/S
// =====================================================================
template <int BM, int BN, int BK, int TM, int TN, int EPI, bool PATCH, bool KCONTIG>
__global__ void __launch_bounds__((BM / TM) * (BN / TN))
trop7(const float* __restrict__ A, int lda, long sA,
      const float* __restrict__ W0, const float* __restrict__ W1,
      const float* __restrict__ W2, int wN, int wK, long sW,
      float* __restrict__ O, int ldo, long sO,
      int M, int Nout, int K, long sM,
      const float* __restrict__ aux, float* __restrict__ mout,
      const float* __restrict__ tau) {
    constexpr int THREADS = (BM / TM) * (BN / TN);
    constexpr int VA = BM * BK / 4;
    constexpr int VB = BN * BK / 4;
    constexpr int ITA = (VA + THREADS - 1) / THREADS;
    constexpr int ITB = (VB + THREADS - 1) / THREADS;

    __shared__ __align__(16) float As[2][BK][BM + 4];
    __shared__ __align__(16) float Bs[2][BK][BN + 4];

    const int z = blockIdx.z;
    A += (long)z * sA;
    O += (long)z * sO;
    const float* W;
    if (W1) W = (z == 0) ? W0 : (z == 1) ? W1 : W2;
    else    W = W0 + (long)z * sW;
    if (aux)  aux  += z * sM;
    if (mout) mout += z * sM;

    const int row0 = blockIdx.x * BM;
    const int n0 = blockIdx.y * BN;
    const int tid = threadIdx.x;

    float4 apf[ITA], bpf[ITB];
    const int nchunks = (K + BK - 1) / BK;

    auto loadA = [&](int c) {
        #pragma unroll
        for (int i = 0; i < ITA; i++) {
            int t = tid + i * THREADS;
            if ((VA % THREADS) && t >= VA) break;
            int flat = t * 4;
            int kk = flat % BK, mm = flat / BK;
            int k = c * BK + kk, r = row0 + mm;
            float4 v;
            if (PATCH) {
                int b = r / N_, n = r % N_;
                int gi = n / G_, gj = n % G_;
                int pi = k >> 4, pj = k & 15;
                v = *reinterpret_cast<const float4*>(
                    &A[((long)b * IMG_ + gi * 16 + pi) * IMG_ + gj * 16 + pj]);
            } else if (r < M) {
                if (k + 3 < K) {
                    v = *reinterpret_cast<const float4*>(&A[(long)r * lda + k]);
                } else {
                    v.x = (k + 0 < K) ? A[(long)r * lda + k + 0] : NEGBIG;
                    v.y = (k + 1 < K) ? A[(long)r * lda + k + 1] : NEGBIG;
                    v.z = (k + 2 < K) ? A[(long)r * lda + k + 2] : NEGBIG;
                    v.w = (k + 3 < K) ? A[(long)r * lda + k + 3] : NEGBIG;
                }
            } else {
                v = make_float4(NEGBIG, NEGBIG, NEGBIG, NEGBIG);
            }
            apf[i] = v;
        }
    };
    auto loadB = [&](int c) {
        #pragma unroll
        for (int i = 0; i < ITB; i++) {
            int t = tid + i * THREADS;
            if ((VB % THREADS) && t >= VB) break;
            int flat = t * 4;
            float4 v;
            if (KCONTIG) {
                int kk = flat % BK;
                int nn = n0 + flat / BK;
                int k = c * BK + kk;
                if (nn < Nout) {
                    v = *reinterpret_cast<const float4*>(&W[(long)nn * wN + k]);
                } else {
                    v = make_float4(NEGBIG, NEGBIG, NEGBIG, NEGBIG);
                }
            } else {
                int n = flat % BN;
                int kk = flat / BN;
                int k = c * BK + kk;
                if (k < K) {
                    v = *reinterpret_cast<const float4*>(&W[(long)k * wK + n0 + n]);
                } else {
                    v = make_float4(NEGBIG, NEGBIG, NEGBIG, NEGBIG);
                }
            }
            bpf[i] = v;
        }
    };
    auto storeAB = [&](int s) {
        #pragma unroll
        for (int i = 0; i < ITA; i++) {
            int t = tid + i * THREADS;
            if ((VA % THREADS) && t >= VA) break;
            int flat = t * 4;
            int kk = flat % BK, mm = flat / BK;
            As[s][kk + 0][mm] = apf[i].x;
            As[s][kk + 1][mm] = apf[i].y;
            As[s][kk + 2][mm] = apf[i].z;
            As[s][kk + 3][mm] = apf[i].w;
        }
        #pragma unroll
        for (int i = 0; i < ITB; i++) {
            int t = tid + i * THREADS;
            if ((VB % THREADS) && t >= VB) break;
            int flat = t * 4;
            if (KCONTIG) {
                int kk = flat % BK, n = flat / BK;
                Bs[s][kk + 0][n] = bpf[i].x;
                Bs[s][kk + 1][n] = bpf[i].y;
                Bs[s][kk + 2][n] = bpf[i].z;
                Bs[s][kk + 3][n] = bpf[i].w;
            } else {
                int n = flat % BN, kk = flat / BN;
                *reinterpret_cast<float4*>(&Bs[s][kk][n]) = bpf[i];
            }
        }
    };

    float acc[TM][TN];
    #pragma unroll
    for (int i = 0; i < TM; i++)
        #pragma unroll
        for (int j = 0; j < TN; j++) acc[i][j] = NEGBIG;

    const int tn = tid & 31;
    const int tm = tid >> 5;

    loadA(0);
    loadB(0);
    storeAB(0);
    __syncthreads();

    for (int c = 0; c < nchunks; c++) {
        const int s = c & 1;
        const bool more = (c + 1 < nchunks);
        if (more) { loadA(c + 1); loadB(c + 1); }
        #pragma unroll
        for (int kk = 0; kk < BK; kk++) {
            float a[TM], b[TN];
            if (TM == 4) *reinterpret_cast<float4*>(a) =
                *reinterpret_cast<const float4*>(&As[s][kk][tm * TM]);
            else if (TM == 2) *reinterpret_cast<float2*>(a) =
                *reinterpret_cast<const float2*>(&As[s][kk][tm * TM]);
            else
                #pragma unroll
                for (int i = 0; i < TM; i++) a[i] = As[s][kk][tm * TM + i];
            if (TN == 4) {
                *reinterpret_cast<float4*>(b) =
                    *reinterpret_cast<const float4*>(&Bs[s][kk][tn * TN]);
            } else {
                *reinterpret_cast<float2*>(b) =
                    *reinterpret_cast<const float2*>(&Bs[s][kk][tn * TN]);
            }
            #pragma unroll
            for (int i = 0; i < TM; i++)
                #pragma unroll
                for (int j = 0; j < TN; j++)
                    acc[i][j] = fmaxf(acc[i][j], a[i] + b[j]);
        }
        if (more) {
            storeAB(s ^ 1);
            __syncthreads();
        }
    }

    float tval = 0.f;
    if (EPI == EPI_SUBROW_TAU) tval = tau[0];

    #pragma unroll
    for (int i = 0; i < TM; i++) {
        int r = row0 + tm * TM + i;
        if (r >= M) continue;
        float sub = 0.f;
        if (EPI == EPI_SUBROW || EPI == EPI_SUBROW_TAU) sub = aux[r];

        float v[TN];
        if (EPI == EPI_RESID_M) {
            float rmax = acc[i][0];
            #pragma unroll
            for (int j = 1; j < TN; j++) rmax = fmaxf(rmax, acc[i][j]);
            #pragma unroll
            for (int off = 16; off; off >>= 1)
                rmax = fmaxf(rmax, __shfl_xor_sync(0xffffffffu, rmax, off));
            #pragma unroll
            for (int j = 0; j < TN; j++) {
                int cc = n0 + tn * TN + j;
                v[j] = fmaxf(O[(long)r * ldo + cc], acc[i][j] - rmax);
            }
        } else if (EPI == EPI_POS_M) {
            #pragma unroll
            for (int j = 0; j < TN; j++) {
                int cc = n0 + tn * TN + j;
                v[j] = acc[i][j] + aux[(r % N_) * ldo + cc];
            }
        } else {
            #pragma unroll
            for (int j = 0; j < TN; j++) {
                float t = acc[i][j];
                if (EPI == EPI_SUBROW) t -= sub;
                else if (EPI == EPI_SUBROW_TAU) t = fmaxf(t - sub, tval);
                v[j] = t;
            }
        }

        #pragma unroll
        for (int j = 0; j < TN; j++) {
            int cc = n0 + tn * TN + j;
            if (cc < Nout) O[(long)r * ldo + cc] = v[j];
        }

        if (EPI == EPI_RESID_M || EPI == EPI_POS_M) {
            float nm = v[0];
            #pragma unroll
            for (int j = 1; j < TN; j++) nm = fmaxf(nm, v[j]);
            #pragma unroll
            for (int off = 16; off; off >>= 1)
                nm = fmaxf(nm, __shfl_xor_sync(0xffffffffu, nm, off));
            if (tn == 0) mout[r] = nm;
        }
    }
}

// =====================================================================
// Template B (R10): BK=32, row-major As, early-O, staging — best for AV
// =====================================================================
template <int BM, int TM, int EPI, bool KCONTIG>
__global__ void __launch_bounds__((BM / TM) * 32)
trop_av(const float* __restrict__ A, int lda, long sA,
        const float* __restrict__ W0, int wN, int wK, long sW,
        float* __restrict__ O, int ldo, long sO,
        int M, int Nout, int K, long sM,
        const float* __restrict__ aux, float* __restrict__ mout) {
    constexpr int BN = 128;
    constexpr int TN = 4;
    constexpr int BK = 32;
    constexpr int THREADS = (BM / TM) * 32;
    constexpr int VA = BM * BK / 4;
    constexpr int VB = BN * BK / 4;
    constexpr int ITA = (VA + THREADS - 1) / THREADS;
    constexpr int ITB = (VB + THREADS - 1) / THREADS;

    __shared__ __align__(16) float As[2][BM][BK + 4];
    __shared__ __align__(16) float Bs[2][BK][BN + 4];

    const int z = blockIdx.z;
    A += (long)z * sA;
    O += (long)z * sO;
    const float* W = W0 + (long)z * sW;
    if (mout) mout += z * sM;

    const int row0 = blockIdx.x * BM;
    const int n0 = blockIdx.y * BN;
    const int tid = threadIdx.x;
    const int tn = tid & 31;
    const int tm = tid >> 5;

    float4 apf[ITA], bpf[ITB];
    const int nchunks = (K + BK - 1) / BK;

    auto loadA = [&](int c) {
        #pragma unroll
        for (int i = 0; i < ITA; i++) {
            int t = tid + i * THREADS;
            if ((VA % THREADS) && t >= VA) break;
            int flat = t * 4;
            int kk = flat % BK, mm = flat / BK;
            int k = c * BK + kk, r = row0 + mm;
            float4 v;
            if (r < M) {
                if (k + 3 < K) {
                    v = *reinterpret_cast<const float4*>(&A[(long)r * lda + k]);
                } else {
                    v.x = (k + 0 < K) ? A[(long)r * lda + k + 0] : NEGBIG;
                    v.y = (k + 1 < K) ? A[(long)r * lda + k + 1] : NEGBIG;
                    v.z = (k + 2 < K) ? A[(long)r * lda + k + 2] : NEGBIG;
                    v.w = (k + 3 < K) ? A[(long)r * lda + k + 3] : NEGBIG;
                }
            } else {
                v = make_float4(NEGBIG, NEGBIG, NEGBIG, NEGBIG);
            }
            apf[i] = v;
        }
    };
    auto loadB = [&](int c) {
        #pragma unroll
        for (int i = 0; i < ITB; i++) {
            int t = tid + i * THREADS;
            if ((VB % THREADS) && t >= VB) break;
            int flat = t * 4;
            float4 v;
            if (KCONTIG) {
                int kk = flat % BK;
                int nn = n0 + flat / BK;
                int k = c * BK + kk;
                if (nn < Nout) {
                    v = *reinterpret_cast<const float4*>(&W[(long)nn * wN + k]);
                } else {
                    v = make_float4(NEGBIG, NEGBIG, NEGBIG, NEGBIG);
                }
            } else {
                int n = flat % BN;
                int kk = flat / BN;
                int k = c * BK + kk;
                if (k < K) {
                    v = *reinterpret_cast<const float4*>(&W[(long)k * wK + n0 + n]);
                } else {
                    v = make_float4(NEGBIG, NEGBIG, NEGBIG, NEGBIG);
                }
            }
            bpf[i] = v;
        }
    };
    auto storeAB = [&](int s) {
        #pragma unroll
        for (int i = 0; i < ITA; i++) {
            int t = tid + i * THREADS;
            if ((VA % THREADS) && t >= VA) break;
            int flat = t * 4;
            int kk = flat % BK, mm = flat / BK;
            *reinterpret_cast<float4*>(&As[s][mm][kk]) = apf[i];
        }
        #pragma unroll
        for (int i = 0; i < ITB; i++) {
            int t = tid + i * THREADS;
            if ((VB % THREADS) && t >= VB) break;
            int flat = t * 4;
            if (KCONTIG) {
                int kk = flat % BK, n = flat / BK;
                Bs[s][kk + 0][n] = bpf[i].x;
                Bs[s][kk + 1][n] = bpf[i].y;
                Bs[s][kk + 2][n] = bpf[i].z;
                Bs[s][kk + 3][n] = bpf[i].w;
            } else {
                int n = flat % BN, kk = flat / BN;
                *reinterpret_cast<float4*>(&Bs[s][kk][n]) = bpf[i];
            }
        }
    };

    float acc[TM][TN];
    #pragma unroll
    for (int i = 0; i < TM; i++)
        #pragma unroll
        for (int j = 0; j < TN; j++) acc[i][j] = NEGBIG;

    float oldv[TM][TN];
    if (EPI == EPI_RESID_M) {
        #pragma unroll
        for (int i = 0; i < TM; i++) {
            int r = row0 + tm * TM + i;
            if (r < M) {
                float4 o4 = *reinterpret_cast<const float4*>(&O[(long)r * ldo + n0 + tn * TN]);
                oldv[i][0] = o4.x; oldv[i][1] = o4.y; oldv[i][2] = o4.z; oldv[i][3] = o4.w;
            }
        }
    }

    loadA(0);
    loadB(0);
    storeAB(0);
    __syncthreads();

    for (int c = 0; c < nchunks; c++) {
        const int s = c & 1;
        const bool more = (c + 1 < nchunks);
        if (more) { loadA(c + 1); loadB(c + 1); }
        #pragma unroll
        for (int g = 0; g < BK / 8; g++) {
            float4 breg[8];
            #pragma unroll
            for (int u = 0; u < 8; u++)
                breg[u] = *reinterpret_cast<const float4*>(&Bs[s][g * 8 + u][tn * TN]);
            float4 areg[TM][2];
            #pragma unroll
            for (int i = 0; i < TM; i++) {
                areg[i][0] = *reinterpret_cast<const float4*>(&As[s][tm * TM + i][g * 8]);
                areg[i][1] = *reinterpret_cast<const float4*>(&As[s][tm * TM + i][g * 8 + 4]);
            }
            #pragma unroll
            for (int u = 0; u < 8; u++) {
                #pragma unroll
                for (int i = 0; i < TM; i++) {
                    float4 ah = areg[i][u >> 2];
                    float av = ((u & 3) == 0) ? ah.x : ((u & 3) == 1) ? ah.y
                             : ((u & 3) == 2) ? ah.z : ah.w;
                    acc[i][0] = fmaxf(acc[i][0], av + breg[u].x);
                    acc[i][1] = fmaxf(acc[i][1], av + breg[u].y);
                    acc[i][2] = fmaxf(acc[i][2], av + breg[u].z);
                    acc[i][3] = fmaxf(acc[i][3], av + breg[u].w);
                }
            }
        }
        if (more) {
            storeAB(s ^ 1);
            __syncthreads();
        }
    }

    #pragma unroll
    for (int i = 0; i < TM; i++) {
        int r = row0 + tm * TM + i;
        if (r >= M) continue;
        float v[TN];
        float rmax = fmaxf(fmaxf(acc[i][0], acc[i][1]), fmaxf(acc[i][2], acc[i][3]));
        #pragma unroll
        for (int off = 16; off; off >>= 1)
            rmax = fmaxf(rmax, __shfl_xor_sync(0xffffffffu, rmax, off));
        #pragma unroll
        for (int j = 0; j < TN; j++)
            v[j] = fmaxf(oldv[i][j], acc[i][j] - rmax);

        #pragma unroll
        for (int j = 0; j < TN; j++)
            O[(long)r * ldo + n0 + tn * TN + j] = v[j];

        float nm = fmaxf(fmaxf(v[0], v[1]), fmaxf(v[2], v[3]));
        #pragma unroll
        for (int off = 16; off; off >>= 1)
            nm = fmaxf(nm, __shfl_xor_sync(0xffffffffu, nm, off));
        if (tn == 0) mout[r] = nm;
    }
}

// =====================================================================
// Fused feed-forward: ffh = max(tropmm(h-m, f1W), tau) in smem, then
// h = max(h, pnorm(tropmm(ffh, f2W))); m = rowmax(h).
// 8 rows per block, 256 threads.
// =====================================================================
__global__ void __launch_bounds__(256)
ff_fused_kernel(float* __restrict__ h, float* __restrict__ m,
                const float* __restrict__ f1W, const float* __restrict__ f2W,
                const float* __restrict__ tau) {
    constexpr int RB = 8;
    __shared__ __align__(16) float Hs[RB][132];      // h rows (K=128)
    __shared__ __align__(16) float FFs[RB][260];     // ffh intermediate (DFF=256)
    __shared__ __align__(16) float BsRaw[2 * 4352];  // phase1: [16][264]; phase2: [32][136]

    const int row0 = blockIdx.x * RB;
    const int tid = threadIdx.x;
    const int w = tid >> 5, tn = tid & 31;

    // phase-2 residual operand, loaded early (row w, 128 cols)
    float4 oldv = *reinterpret_cast<const float4*>(&h[(long)(row0 + w) * D_ + tn * 4]);

    // phase-1 row constants
    const int ch = w >> 2;             // column half (0/1) of DFF
    const int rw0 = (w & 3) * 2;       // two rows per warp
    const float msub0 = m[row0 + rw0];
    const float msub1 = m[row0 + rw0 + 1];
    const float tval = tau[0];

    // ---- load H rows into smem (1 float4/thread) ----
    {
        int flat = tid * 4;
        int r = flat >> 7, k = flat & 127;
        *reinterpret_cast<float4*>(&Hs[r][k]) =
            *reinterpret_cast<const float4*>(&h[(long)(row0 + r) * D_ + k]);
    }

    // ---- phase 1: ffh = max(tropmm(h, f1W) - m, tau) ----
    // Bs1 view: [s][kk][n], stride 264, BK=16, n in [0,256)
    auto bs1 = [&](int s, int kk, int n) -> float& {
        return BsRaw[s * 4352 + kk * 264 + n];
    };
    float4 bpf[4];
    auto ldB1 = [&](int c) {
        #pragma unroll
        for (int i = 0; i < 4; i++) {
            int flat = (tid + i * 256) * 4;
            int kk = flat & 15, n = flat >> 4;
            bpf[i] = *reinterpret_cast<const float4*>(&f1W[(long)n * D_ + c * 16 + kk]);
        }
    };
    auto stB1 = [&](int s) {
        #pragma unroll
        for (int i = 0; i < 4; i++) {
            int flat = (tid + i * 256) * 4;
            int kk = flat & 15, n = flat >> 4;
            bs1(s, kk + 0, n) = bpf[i].x;
            bs1(s, kk + 1, n) = bpf[i].y;
            bs1(s, kk + 2, n) = bpf[i].z;
            bs1(s, kk + 3, n) = bpf[i].w;
        }
    };

    float acc1[2][4];
    #pragma unroll
    for (int i = 0; i < 2; i++)
        #pragma unroll
        for (int j = 0; j < 4; j++) acc1[i][j] = NEGBIG;

    ldB1(0);
    stB1(0);
    __syncthreads();   // covers Hs + first Bs1

    #pragma unroll
    for (int c = 0; c < 8; c++) {           // K=128, BK=16
        const int s = c & 1;
        const bool more = (c < 7);
        if (more) ldB1(c + 1);
        #pragma unroll
        for (int q = 0; q < 4; q++) {
            float4 a0 = *reinterpret_cast<const float4*>(&Hs[rw0][c * 16 + q * 4]);
            float4 a1 = *reinterpret_cast<const float4*>(&Hs[rw0 + 1][c * 16 + q * 4]);
            #pragma unroll
            for (int u = 0; u < 4; u++) {
                float4 b = *reinterpret_cast<const float4*>(&bs1(s, q * 4 + u, ch * 128 + tn * 4));
                float av0 = (u == 0) ? a0.x : (u == 1) ? a0.y : (u == 2) ? a0.z : a0.w;
                float av1 = (u == 0) ? a1.x : (u == 1) ? a1.y : (u == 2) ? a1.z : a1.w;
                acc1[0][0] = fmaxf(acc1[0][0], av0 + b.x);
                acc1[0][1] = fmaxf(acc1[0][1], av0 + b.y);
                acc1[0][2] = fmaxf(acc1[0][2], av0 + b.z);
                acc1[0][3] = fmaxf(acc1[0][3], av0 + b.w);
                acc1[1][0] = fmaxf(acc1[1][0], av1 + b.x);
                acc1[1][1] = fmaxf(acc1[1][1], av1 + b.y);
                acc1[1][2] = fmaxf(acc1[1][2], av1 + b.z);
                acc1[1][3] = fmaxf(acc1[1][3], av1 + b.w);
            }
        }
        if (more) {
            stB1(s ^ 1);
            __syncthreads();
        }
    }

    // store ffh to smem (apply -m and tau)
    {
        float4 f0, f1;
        f0.x = fmaxf(acc1[0][0] - msub0, tval);
        f0.y = fmaxf(acc1[0][1] - msub0, tval);
        f0.z = fmaxf(acc1[0][2] - msub0, tval);
        f0.w = fmaxf(acc1[0][3] - msub0, tval);
        f1.x = fmaxf(acc1[1][0] - msub1, tval);
        f1.y = fmaxf(acc1[1][1] - msub1, tval);
        f1.z = fmaxf(acc1[1][2] - msub1, tval);
        f1.w = fmaxf(acc1[1][3] - msub1, tval);
        *reinterpret_cast<float4*>(&FFs[rw0][ch * 128 + tn * 4]) = f0;
        *reinterpret_cast<float4*>(&FFs[rw0 + 1][ch * 128 + tn * 4]) = f1;
    }
    __syncthreads();   // phase boundary: FFs ready, Bs1 free

    // ---- phase 2: h = max(h, pnorm(tropmm(ffh, f2W))); m = rowmax ----
    // Bs2 view: [s][kk][d], stride 136, BK=32, d in [0,128)
    auto bs2 = [&](int s, int kk, int d) -> float& {
        return BsRaw[s * 4352 + kk * 136 + d];
    };
    auto ldB2 = [&](int c) {
        #pragma unroll
        for (int i = 0; i < 4; i++) {
            int flat = (tid + i * 256) * 4;
            int kk = flat & 31, d = flat >> 5;
            bpf[i] = *reinterpret_cast<const float4*>(&f2W[(long)d * DFF_ + c * 32 + kk]);
        }
    };
    auto stB2 = [&](int s) {
        #pragma unroll
        for (int i = 0; i < 4; i++) {
            int flat = (tid + i * 256) * 4;
            int kk = flat & 31, d = flat >> 5;
            bs2(s, kk + 0, d) = bpf[i].x;
            bs2(s, kk + 1, d) = bpf[i].y;
            bs2(s, kk + 2, d) = bpf[i].z;
            bs2(s, kk + 3, d) = bpf[i].w;
        }
    };

    float acc2[4] = {NEGBIG, NEGBIG, NEGBIG, NEGBIG};

    ldB2(0);
    stB2(0);
    __syncthreads();

    #pragma unroll
    for (int c = 0; c < 8; c++) {           // K=256, BK=32
        const int s = c & 1;
        const bool more = (c < 7);
        if (more) ldB2(c + 1);
        #pragma unroll
        for (int q = 0; q < 8; q++) {
            float4 a4 = *reinterpret_cast<const float4*>(&FFs[w][c * 32 + q * 4]);
            #pragma unroll
            for (int u = 0; u < 4; u++) {
                float4 b = *reinterpret_cast<const float4*>(&bs2(s, q * 4 + u, tn * 4));
                float av = (u == 0) ? a4.x : (u == 1) ? a4.y : (u == 2) ? a4.z : a4.w;
                acc2[0] = fmaxf(acc2[0], av + b.x);
                acc2[1] = fmaxf(acc2[1], av + b.y);
                acc2[2] = fmaxf(acc2[2], av + b.z);
                acc2[3] = fmaxf(acc2[3], av + b.w);
            }
        }
        if (more) {
            stB2(s ^ 1);
            __syncthreads();
        }
    }

    // epilogue: pnorm + residual + new rowmax
    float rmax = fmaxf(fmaxf(acc2[0], acc2[1]), fmaxf(acc2[2], acc2[3]));
    #pragma unroll
    for (int off = 16; off; off >>= 1)
        rmax = fmaxf(rmax, __shfl_xor_sync(0xffffffffu, rmax, off));

    float4 outv;
    outv.x = fmaxf(oldv.x, acc2[0] - rmax);
    outv.y = fmaxf(oldv.y, acc2[1] - rmax);
    outv.z = fmaxf(oldv.z, acc2[2] - rmax);
    outv.w = fmaxf(oldv.w, acc2[3] - rmax);
    *reinterpret_cast<float4*>(&h[(long)(row0 + w) * D_ + tn * 4]) = outv;

    float nm = fmaxf(fmaxf(outv.x, outv.y), fmaxf(outv.z, outv.w));
    #pragma unroll
    for (int off = 16; off; off >>= 1)
        nm = fmaxf(nm, __shfl_xor_sync(0xffffffffu, nm, off));
    if (tn == 0) m[row0 + w] = nm;
}

// ---------------- tropical global pool over patches ----------------
__global__ void pool_kernel(const float* __restrict__ h, float* __restrict__ pool) {
    int idx = blockIdx.x * blockDim.x + threadIdx.x;
    if (idx >= B_ * D_) return;
    int d = idx % D_, b = idx / D_;
    float v = NEGBIG;
    for (int n = 0; n < N_; n++) v = fmaxf(v, h[((long)b * N_ + n) * D_ + d]);
    pool[idx] = v;
}

// ---------------- head ----------------
__global__ void head_kernel(const float* __restrict__ pool, const float* __restrict__ W,
                            const float* __restrict__ scale, float* __restrict__ out) {
    int gw = (blockIdx.x * blockDim.x + threadIdx.x) >> 5;
    int lane = threadIdx.x & 31;
    if (gw >= B_ * C_) return;
    int c = gw % C_, b = gw / C_;
    float v = NEGBIG;
    #pragma unroll
    for (int i = 0; i < 4; i++) {
        int d = lane + i * 32;
        v = fmaxf(v, pool[b * D_ + d] + W[(long)c * D_ + d]);
    }
    #pragma unroll
    for (int off = 16; off; off >>= 1) v = fmaxf(v, __shfl_xor_sync(0xffffffffu, v, off));
    if (lane == 0) out[gw] = v * scale[0];
}

// ---------------- host ----------------
extern "C" void kernel_launch(void* const* d_in, const int* in_sizes, int n_in,
                              void* d_out, int out_size) {
    const float* x       = (const float*)d_in[0];
    const float* embed_W = (const float*)d_in[1];
    const float* pos     = (const float*)d_in[2];
    const float* qW[2]   = {(const float*)d_in[3],  (const float*)d_in[9]};
    const float* kW[2]   = {(const float*)d_in[4],  (const float*)d_in[10]};
    const float* vW[2]   = {(const float*)d_in[5],  (const float*)d_in[11]};
    const float* f1W[2]  = {(const float*)d_in[6],  (const float*)d_in[12]};
    const float* f2W[2]  = {(const float*)d_in[7],  (const float*)d_in[13]};
    const float* tau[2]  = {(const float*)d_in[8],  (const float*)d_in[14]};
    const float* headW   = (const float*)d_in[15];
    const float* lscale  = (const float*)d_in[16];
    float* out = (float*)d_out;

    float *p_h, *p_qkv, *p_S, *p_m, *p_pool;
    cudaGetSymbolAddress((void**)&p_h, g_h);
    cudaGetSymbolAddress((void**)&p_qkv, g_qkv);
    cudaGetSymbolAddress((void**)&p_S, g_S);
    cudaGetSymbolAddress((void**)&p_m, g_m);
    cudaGetSymbolAddress((void**)&p_pool, g_pool);

    const long tokD = (long)N_ * D_;
    const long qkvS = (long)M_ * D_;
    float* p_m_ = p_m;

    // embed (patchify fused): h = tropmm(patches, embed_W) + pos; m = rowmax(h)
    trop7<8, 128, 16, 2, 4, EPI_POS_M, true, true><<<dim3(196, 1, 1), 128>>>(
        x, 0, 0, embed_W, nullptr, nullptr, PD_, 1, 0,
        p_h, D_, 0, M_, D_, PD_, 0, pos, p_m_, nullptr);

    for (int l = 0; l < 2; l++) {
        // q/k/v = tropmm(h, W) - m
        trop7<16, 128, 16, 2, 4, EPI_SUBROW, false, true><<<dim3(98, 1, 3), 256>>>(
            p_h, D_, 0, qW[l], kW[l], vW[l], D_, 1, 0,
            p_qkv, D_, qkvS, M_, D_, D_, 0, p_m, nullptr, nullptr);

        // S[b,i,j] = max_d(q_id + k_jd)
        trop7<16, 64, 16, 4, 2, EPI_STORE, false, true><<<dim3(13, 4, 8), 128>>>(
            p_qkv, D_, tokD, p_qkv + qkvS, nullptr, nullptr, D_, 1, tokD,
            p_S, N_, (long)N_ * N_, N_, N_, D_, 0, nullptr, nullptr, nullptr);

        // h = max(h, pnorm(max_j(S + v)));  m = rowmax(h)
        trop_av<8, 2, EPI_RESID_M, false><<<dim3(25, 1, 8), 128>>>(
            p_S, N_, (long)N_ * N_, p_qkv + 2 * qkvS, 1, D_, tokD,
            p_h, D_, tokD, N_, D_, N_, N_, nullptr, p_m);

        // fused ff1+ff2: h = max(h, pnorm(tropmm(max(tropmm(h-m,f1W),tau), f2W))); m updated
        ff_fused_kernel<<<196, 256>>>(p_h, p_m, f1W[l], f2W[l], tau[l]);
    }

    pool_kernel<<<8, 128>>>(p_h, p_pool);
    head_kernel<<<1000, 256>>>(p_pool, headW, lscale, out);
}

// round 12
// speedup vs baseline: 1.1120x; 1.1120x over previous
#include <cuda_runtime.h>

// ---------------- problem dims ----------------
constexpr int B_   = 8;
constexpr int IMG_ = 224;
constexpr int G_   = 14;
constexpr int N_   = 196;   // G*G patches
constexpr int PD_  = 256;   // 16*16 patch dim
constexpr int D_   = 128;
constexpr int DFF_ = 256;
constexpr int C_   = 1000;
constexpr int M_   = B_ * N_;   // 1568 token rows

constexpr float NEGBIG = -1e30f;

// ---------------- scratch ----------------
__device__ float g_h[M_ * D_];
__device__ float g_qkv[3 * M_ * D_];
__device__ float g_S[B_ * N_ * N_];
__device__ float g_ff[M_ * DFF_];
__device__ float g_m[M_];
__device__ float g_pool[B_ * D_];

// epilogue modes
enum {
    EPI_STORE = 0,
    EPI_POS_M = 1,
    EPI_SUBROW = 2,
    EPI_SUBROW_TAU = 3,
    EPI_RESID_M = 4
};

// =====================================================================
// Template A (R7-exact): BK=16, column-major As — embed/qkv/S/ff1/ff2
// =====================================================================
template <int BM, int BN, int BK, int TM, int TN, int EPI, bool PATCH, bool KCONTIG>
__global__ void __launch_bounds__((BM / TM) * (BN / TN))
trop7(const float* __restrict__ A, int lda, long sA,
      const float* __restrict__ W0, const float* __restrict__ W1,
      const float* __restrict__ W2, int wN, int wK, long sW,
      float* __restrict__ O, int ldo, long sO,
      int M, int Nout, int K, long sM,
      const float* __restrict__ aux, float* __restrict__ mout,
      const float* __restrict__ tau) {
    constexpr int THREADS = (BM / TM) * (BN / TN);
    constexpr int VA = BM * BK / 4;
    constexpr int VB = BN * BK / 4;
    constexpr int ITA = (VA + THREADS - 1) / THREADS;
    constexpr int ITB = (VB + THREADS - 1) / THREADS;

    __shared__ __align__(16) float As[2][BK][BM + 4];
    __shared__ __align__(16) float Bs[2][BK][BN + 4];

    const int z = blockIdx.z;
    A += (long)z * sA;
    O += (long)z * sO;
    const float* W;
    if (W1) W = (z == 0) ? W0 : (z == 1) ? W1 : W2;
    else    W = W0 + (long)z * sW;
    if (aux)  aux  += z * sM;
    if (mout) mout += z * sM;

    const int row0 = blockIdx.x * BM;
    const int n0 = blockIdx.y * BN;
    const int tid = threadIdx.x;

    float4 apf[ITA], bpf[ITB];
    const int nchunks = (K + BK - 1) / BK;

    auto loadA = [&](int c) {
        #pragma unroll
        for (int i = 0; i < ITA; i++) {
            int t = tid + i * THREADS;
            if ((VA % THREADS) && t >= VA) break;
            int flat = t * 4;
            int kk = flat % BK, mm = flat / BK;
            int k = c * BK + kk, r = row0 + mm;
            float4 v;
            if (PATCH) {
                int b = r / N_, n = r % N_;
                int gi = n / G_, gj = n % G_;
                int pi = k >> 4, pj = k & 15;
                v = *reinterpret_cast<const float4*>(
                    &A[((long)b * IMG_ + gi * 16 + pi) * IMG_ + gj * 16 + pj]);
            } else if (r < M) {
                if (k + 3 < K) {
                    v = *reinterpret_cast<const float4*>(&A[(long)r * lda + k]);
                } else {
                    v.x = (k + 0 < K) ? A[(long)r * lda + k + 0] : NEGBIG;
                    v.y = (k + 1 < K) ? A[(long)r * lda + k + 1] : NEGBIG;
                    v.z = (k + 2 < K) ? A[(long)r * lda + k + 2] : NEGBIG;
                    v.w = (k + 3 < K) ? A[(long)r * lda + k + 3] : NEGBIG;
                }
            } else {
                v = make_float4(NEGBIG, NEGBIG, NEGBIG, NEGBIG);
            }
            apf[i] = v;
        }
    };
    auto loadB = [&](int c) {
        #pragma unroll
        for (int i = 0; i < ITB; i++) {
            int t = tid + i * THREADS;
            if ((VB % THREADS) && t >= VB) break;
            int flat = t * 4;
            float4 v;
            if (KCONTIG) {
                int kk = flat % BK;
                int nn = n0 + flat / BK;
                int k = c * BK + kk;
                if (nn < Nout) {
                    v = *reinterpret_cast<const float4*>(&W[(long)nn * wN + k]);
                } else {
                    v = make_float4(NEGBIG, NEGBIG, NEGBIG, NEGBIG);
                }
            } else {
                int n = flat % BN;
                int kk = flat / BN;
                int k = c * BK + kk;
                if (k < K) {
                    v = *reinterpret_cast<const float4*>(&W[(long)k * wK + n0 + n]);
                } else {
                    v = make_float4(NEGBIG, NEGBIG, NEGBIG, NEGBIG);
                }
            }
            bpf[i] = v;
        }
    };
    auto storeAB = [&](int s) {
        #pragma unroll
        for (int i = 0; i < ITA; i++) {
            int t = tid + i * THREADS;
            if ((VA % THREADS) && t >= VA) break;
            int flat = t * 4;
            int kk = flat % BK, mm = flat / BK;
            As[s][kk + 0][mm] = apf[i].x;
            As[s][kk + 1][mm] = apf[i].y;
            As[s][kk + 2][mm] = apf[i].z;
            As[s][kk + 3][mm] = apf[i].w;
        }
        #pragma unroll
        for (int i = 0; i < ITB; i++) {
            int t = tid + i * THREADS;
            if ((VB % THREADS) && t >= VB) break;
            int flat = t * 4;
            if (KCONTIG) {
                int kk = flat % BK, n = flat / BK;
                Bs[s][kk + 0][n] = bpf[i].x;
                Bs[s][kk + 1][n] = bpf[i].y;
                Bs[s][kk + 2][n] = bpf[i].z;
                Bs[s][kk + 3][n] = bpf[i].w;
            } else {
                int n = flat % BN, kk = flat / BN;
                *reinterpret_cast<float4*>(&Bs[s][kk][n]) = bpf[i];
            }
        }
    };

    float acc[TM][TN];
    #pragma unroll
    for (int i = 0; i < TM; i++)
        #pragma unroll
        for (int j = 0; j < TN; j++) acc[i][j] = NEGBIG;

    const int tn = tid & 31;
    const int tm = tid >> 5;

    loadA(0);
    loadB(0);
    storeAB(0);
    __syncthreads();

    for (int c = 0; c < nchunks; c++) {
        const int s = c & 1;
        const bool more = (c + 1 < nchunks);
        if (more) { loadA(c + 1); loadB(c + 1); }
        #pragma unroll
        for (int kk = 0; kk < BK; kk++) {
            float a[TM], b[TN];
            if (TM == 4) *reinterpret_cast<float4*>(a) =
                *reinterpret_cast<const float4*>(&As[s][kk][tm * TM]);
            else if (TM == 2) *reinterpret_cast<float2*>(a) =
                *reinterpret_cast<const float2*>(&As[s][kk][tm * TM]);
            else
                #pragma unroll
                for (int i = 0; i < TM; i++) a[i] = As[s][kk][tm * TM + i];
            if (TN == 4) {
                *reinterpret_cast<float4*>(b) =
                    *reinterpret_cast<const float4*>(&Bs[s][kk][tn * TN]);
            } else {
                *reinterpret_cast<float2*>(b) =
                    *reinterpret_cast<const float2*>(&Bs[s][kk][tn * TN]);
            }
            #pragma unroll
            for (int i = 0; i < TM; i++)
                #pragma unroll
                for (int j = 0; j < TN; j++)
                    acc[i][j] = fmaxf(acc[i][j], a[i] + b[j]);
        }
        if (more) {
            storeAB(s ^ 1);
            __syncthreads();
        }
    }

    float tval = 0.f;
    if (EPI == EPI_SUBROW_TAU) tval = tau[0];

    #pragma unroll
    for (int i = 0; i < TM; i++) {
        int r = row0 + tm * TM + i;
        if (r >= M) continue;
        float sub = 0.f;
        if (EPI == EPI_SUBROW || EPI == EPI_SUBROW_TAU) sub = aux[r];

        float v[TN];
        if (EPI == EPI_RESID_M) {
            float rmax = acc[i][0];
            #pragma unroll
            for (int j = 1; j < TN; j++) rmax = fmaxf(rmax, acc[i][j]);
            #pragma unroll
            for (int off = 16; off; off >>= 1)
                rmax = fmaxf(rmax, __shfl_xor_sync(0xffffffffu, rmax, off));
            #pragma unroll
            for (int j = 0; j < TN; j++) {
                int cc = n0 + tn * TN + j;
                v[j] = fmaxf(O[(long)r * ldo + cc], acc[i][j] - rmax);
            }
        } else if (EPI == EPI_POS_M) {
            #pragma unroll
            for (int j = 0; j < TN; j++) {
                int cc = n0 + tn * TN + j;
                v[j] = acc[i][j] + aux[(r % N_) * ldo + cc];
            }
        } else {
            #pragma unroll
            for (int j = 0; j < TN; j++) {
                float t = acc[i][j];
                if (EPI == EPI_SUBROW) t -= sub;
                else if (EPI == EPI_SUBROW_TAU) t = fmaxf(t - sub, tval);
                v[j] = t;
            }
        }

        #pragma unroll
        for (int j = 0; j < TN; j++) {
            int cc = n0 + tn * TN + j;
            if (cc < Nout) O[(long)r * ldo + cc] = v[j];
        }

        if (EPI == EPI_RESID_M || EPI == EPI_POS_M) {
            float nm = v[0];
            #pragma unroll
            for (int j = 1; j < TN; j++) nm = fmaxf(nm, v[j]);
            #pragma unroll
            for (int off = 16; off; off >>= 1)
                nm = fmaxf(nm, __shfl_xor_sync(0xffffffffu, nm, off));
            if (tn == 0) mout[r] = nm;
        }
    }
}

// =====================================================================
// AV kernel, column-split: 256 threads, warp = 2 rows x 64 cols.
// h = max(h, pnorm(max_k(S[r,k] + V[k,d])));  m = rowmax(h).
// =====================================================================
template <int BM>
__global__ void __launch_bounds__(256)
trop_av2(const float* __restrict__ A, int lda, long sA,      // S
         const float* __restrict__ Vv, long sV,              // v (K x 128, row-major)
         float* __restrict__ O, int ldo, long sO,            // h
         int M, int K, long sM, float* __restrict__ mout) {
    constexpr int BN = 128, BK = 32, TM = 2;
    constexpr int THREADS = 256;
    constexpr int VA = BM * BK / 4;      // 64
    constexpr int VB = BN * BK / 4;      // 1024
    constexpr int ITB = VB / THREADS;    // 4

    __shared__ __align__(16) float As[2][BM][BK + 4];
    __shared__ __align__(16) float Bs[2][BK][BN + 4];
    __shared__ float red0[BM][2], red1[BM][2];

    const int z = blockIdx.z;
    A += (long)z * sA;
    O += (long)z * sO;
    const float* W = Vv + (long)z * sV;
    mout += z * sM;

    const int row0 = blockIdx.x * BM;
    const int tid = threadIdx.x;
    const int tn = tid & 31;
    const int w = tid >> 5;
    const int chalf = w & 1;          // column half: 0 -> [0,64), 1 -> [64,128)
    const int pair = w >> 1;          // 0..3
    const int rl = pair * TM;         // local row base
    const int colb = chalf * 64 + tn * 2;

    float4 apf;
    float4 bpf[ITB];
    const int nchunks = (K + BK - 1) / BK;

    auto loadA = [&](int c) {
        if (tid < VA) {
            int flat = tid * 4;
            int kk = flat % BK, mm = flat / BK;
            int k = c * BK + kk, r = row0 + mm;
            float4 v;
            if (r < M) {
                if (k + 3 < K) {
                    v = *reinterpret_cast<const float4*>(&A[(long)r * lda + k]);
                } else {
                    v.x = (k + 0 < K) ? A[(long)r * lda + k + 0] : NEGBIG;
                    v.y = (k + 1 < K) ? A[(long)r * lda + k + 1] : NEGBIG;
                    v.z = (k + 2 < K) ? A[(long)r * lda + k + 2] : NEGBIG;
                    v.w = (k + 3 < K) ? A[(long)r * lda + k + 3] : NEGBIG;
                }
            } else {
                v = make_float4(NEGBIG, NEGBIG, NEGBIG, NEGBIG);
            }
            apf = v;
        }
    };
    auto loadB = [&](int c) {
        #pragma unroll
        for (int i = 0; i < ITB; i++) {
            int flat = (tid + i * THREADS) * 4;
            int n = flat % BN, kk = flat / BN;
            int k = c * BK + kk;
            bpf[i] = (k < K)
                ? *reinterpret_cast<const float4*>(&W[(long)k * D_ + n])
                : make_float4(NEGBIG, NEGBIG, NEGBIG, NEGBIG);
        }
    };
    auto storeAB = [&](int s) {
        if (tid < VA) {
            int flat = tid * 4;
            int kk = flat % BK, mm = flat / BK;
            *reinterpret_cast<float4*>(&As[s][mm][kk]) = apf;
        }
        #pragma unroll
        for (int i = 0; i < ITB; i++) {
            int flat = (tid + i * THREADS) * 4;
            int n = flat % BN, kk = flat / BN;
            *reinterpret_cast<float4*>(&Bs[s][kk][n]) = bpf[i];
        }
    };

    float acc[TM][2];
    #pragma unroll
    for (int i = 0; i < TM; i++) { acc[i][0] = NEGBIG; acc[i][1] = NEGBIG; }

    // early residual read
    float2 oldv[TM];
    #pragma unroll
    for (int i = 0; i < TM; i++) {
        int r = row0 + rl + i;
        if (r < M) oldv[i] = *reinterpret_cast<const float2*>(&O[(long)r * ldo + colb]);
    }

    loadA(0);
    loadB(0);
    storeAB(0);
    __syncthreads();

    for (int c = 0; c < nchunks; c++) {
        const int s = c & 1;
        const bool more = (c + 1 < nchunks);
        if (more) { loadA(c + 1); loadB(c + 1); }
        #pragma unroll
        for (int g = 0; g < BK / 8; g++) {
            float2 breg[8];
            #pragma unroll
            for (int u = 0; u < 8; u++)
                breg[u] = *reinterpret_cast<const float2*>(&Bs[s][g * 8 + u][colb]);
            float4 areg[TM][2];
            #pragma unroll
            for (int i = 0; i < TM; i++) {
                areg[i][0] = *reinterpret_cast<const float4*>(&As[s][rl + i][g * 8]);
                areg[i][1] = *reinterpret_cast<const float4*>(&As[s][rl + i][g * 8 + 4]);
            }
            #pragma unroll
            for (int u = 0; u < 8; u++) {
                #pragma unroll
                for (int i = 0; i < TM; i++) {
                    float4 ah = areg[i][u >> 2];
                    float av = ((u & 3) == 0) ? ah.x : ((u & 3) == 1) ? ah.y
                             : ((u & 3) == 2) ? ah.z : ah.w;
                    acc[i][0] = fmaxf(acc[i][0], av + breg[u].x);
                    acc[i][1] = fmaxf(acc[i][1], av + breg[u].y);
                }
            }
        }
        if (more) {
            storeAB(s ^ 1);
            __syncthreads();
        }
    }

    // ---- epilogue: two-stage rowmax (64-col warp reduce + 2-half combine) ----
    #pragma unroll
    for (int i = 0; i < TM; i++) {
        float p = fmaxf(acc[i][0], acc[i][1]);
        #pragma unroll
        for (int off = 16; off; off >>= 1)
            p = fmaxf(p, __shfl_xor_sync(0xffffffffu, p, off));
        if (tn == 0) red0[rl + i][chalf] = p;
    }
    __syncthreads();

    float v[TM][2];
    #pragma unroll
    for (int i = 0; i < TM; i++) {
        float rmax = fmaxf(red0[rl + i][0], red0[rl + i][1]);
        v[i][0] = fmaxf(oldv[i].x, acc[i][0] - rmax);
        v[i][1] = fmaxf(oldv[i].y, acc[i][1] - rmax);
        float nm = fmaxf(v[i][0], v[i][1]);
        #pragma unroll
        for (int off = 16; off; off >>= 1)
            nm = fmaxf(nm, __shfl_xor_sync(0xffffffffu, nm, off));
        if (tn == 0) red1[rl + i][chalf] = nm;
        int r = row0 + rl + i;
        if (r < M) {
            float2 ov; ov.x = v[i][0]; ov.y = v[i][1];
            *reinterpret_cast<float2*>(&O[(long)r * ldo + colb]) = ov;
        }
    }
    __syncthreads();

    if (tn == 0 && chalf == 0) {
        #pragma unroll
        for (int i = 0; i < TM; i++) {
            int r = row0 + rl + i;
            if (r < M) mout[r] = fmaxf(red1[rl + i][0], red1[rl + i][1]);
        }
    }
}

// ---------------- tropical global pool over patches ----------------
__global__ void pool_kernel(const float* __restrict__ h, float* __restrict__ pool) {
    int idx = blockIdx.x * blockDim.x + threadIdx.x;
    if (idx >= B_ * D_) return;
    int d = idx % D_, b = idx / D_;
    float v = NEGBIG;
    for (int n = 0; n < N_; n++) v = fmaxf(v, h[((long)b * N_ + n) * D_ + d]);
    pool[idx] = v;
}

// ---------------- head ----------------
__global__ void head_kernel(const float* __restrict__ pool, const float* __restrict__ W,
                            const float* __restrict__ scale, float* __restrict__ out) {
    int gw = (blockIdx.x * blockDim.x + threadIdx.x) >> 5;
    int lane = threadIdx.x & 31;
    if (gw >= B_ * C_) return;
    int c = gw % C_, b = gw / C_;
    float v = NEGBIG;
    #pragma unroll
    for (int i = 0; i < 4; i++) {
        int d = lane + i * 32;
        v = fmaxf(v, pool[b * D_ + d] + W[(long)c * D_ + d]);
    }
    #pragma unroll
    for (int off = 16; off; off >>= 1) v = fmaxf(v, __shfl_xor_sync(0xffffffffu, v, off));
    if (lane == 0) out[gw] = v * scale[0];
}

// ---------------- host ----------------
extern "C" void kernel_launch(void* const* d_in, const int* in_sizes, int n_in,
                              void* d_out, int out_size) {
    const float* x       = (const float*)d_in[0];
    const float* embed_W = (const float*)d_in[1];
    const float* pos     = (const float*)d_in[2];
    const float* qW[2]   = {(const float*)d_in[3],  (const float*)d_in[9]};
    const float* kW[2]   = {(const float*)d_in[4],  (const float*)d_in[10]};
    const float* vW[2]   = {(const float*)d_in[5],  (const float*)d_in[11]};
    const float* f1W[2]  = {(const float*)d_in[6],  (const float*)d_in[12]};
    const float* f2W[2]  = {(const float*)d_in[7],  (const float*)d_in[13]};
    const float* tau[2]  = {(const float*)d_in[8],  (const float*)d_in[14]};
    const float* headW   = (const float*)d_in[15];
    const float* lscale  = (const float*)d_in[16];
    float* out = (float*)d_out;

    float *p_h, *p_qkv, *p_S, *p_ff, *p_m, *p_pool;
    cudaGetSymbolAddress((void**)&p_h, g_h);
    cudaGetSymbolAddress((void**)&p_qkv, g_qkv);
    cudaGetSymbolAddress((void**)&p_S, g_S);
    cudaGetSymbolAddress((void**)&p_ff, g_ff);
    cudaGetSymbolAddress((void**)&p_m, g_m);
    cudaGetSymbolAddress((void**)&p_pool, g_pool);

    const long tokD = (long)N_ * D_;
    const long qkvS = (long)M_ * D_;

    // embed (patchify fused): h = tropmm(patches, embed_W) + pos; m = rowmax(h)
    trop7<8, 128, 16, 2, 4, EPI_POS_M, true, true><<<dim3(196, 1, 1), 128>>>(
        x, 0, 0, embed_W, nullptr, nullptr, PD_, 1, 0,
        p_h, D_, 0, M_, D_, PD_, 0, pos, p_m, nullptr);

    for (int l = 0; l < 2; l++) {
        // q/k/v = tropmm(h, W) - m
        trop7<16, 128, 16, 2, 4, EPI_SUBROW, false, true><<<dim3(98, 1, 3), 256>>>(
            p_h, D_, 0, qW[l], kW[l], vW[l], D_, 1, 0,
            p_qkv, D_, qkvS, M_, D_, D_, 0, p_m, nullptr, nullptr);

        // S[b,i,j] = max_d(q_id + k_jd)
        trop7<16, 64, 16, 4, 2, EPI_STORE, false, true><<<dim3(13, 4, 8), 128>>>(
            p_qkv, D_, tokD, p_qkv + qkvS, nullptr, nullptr, D_, 1, tokD,
            p_S, N_, (long)N_ * N_, N_, N_, D_, 0, nullptr, nullptr, nullptr);

        // h = max(h, pnorm(max_j(S + v)));  m = rowmax(h) — col-split, 256 thr
        trop_av2<8><<<dim3(25, 1, 8), 256>>>(
            p_S, N_, (long)N_ * N_, p_qkv + 2 * qkvS, tokD,
            p_h, D_, tokD, N_, N_, N_, p_m);

        // ff = max(tropmm(h, f1W) - m, tau)
        trop7<8, 128, 16, 2, 4, EPI_SUBROW_TAU, false, true><<<dim3(196, 2, 1), 128>>>(
            p_h, D_, 0, f1W[l], nullptr, nullptr, D_, 1, 0,
            p_ff, DFF_, 0, M_, DFF_, D_, 0, p_m, nullptr, tau[l]);

        // h = max(h, pnorm(tropmm(ff, f2W)));  m = rowmax(h)
        trop7<8, 128, 16, 2, 4, EPI_RESID_M, false, true><<<dim3(196, 1, 1), 128>>>(
            p_ff, DFF_, 0, f2W[l], nullptr, nullptr, DFF_, 1, 0,
            p_h, D_, 0, M_, D_, DFF_, 0, nullptr, p_m, nullptr);
    }

    pool_kernel<<<8, 128>>>(p_h, p_pool);
    head_kernel<<<1000, 256>>>(p_pool, headW, lscale, out);
}